// round 17
// baseline (speedup 1.0000x reference)
#include <cuda_runtime.h>
#include <math.h>

#define N_ 16384
#define D_ 2048
#define H_ 1024

// fp32(exp(-100)) = 27 * 2^-149 (subnormal), bit pattern 0x0000001B.
#define CLIP_P_BITS 27u

// ---------------- scratch (device globals; no allocation allowed) ----------
__device__ int   g_max640_bits;    // atomicMax of prefix-640 mu norms (>=0)
__device__ int   g_max1024_bits;   // atomicMax of prefix-1024 mu norms (>=0)
__device__ int   g_count;          // last-block-done counter (self-resetting)
__device__ float g_maxsd2;
__device__ float g_yconst;         // y for a clipped row
__device__ float g_th640;          // row clips if prefix-640 x2 > this
__device__ float g_th1024;         // row clips if prefix-1024 x2 > this

// Non-FTZ fp32 ops (immune to any -ftz / fast-math compile flags).
__device__ __forceinline__ float mul_rn(float a, float b) {
    float c; asm("mul.rn.f32 %0, %1, %2;" : "=f"(c) : "f"(a), "f"(b)); return c;
}
__device__ __forceinline__ float add_rn(float a, float b) {
    float c; asm("add.rn.f32 %0, %1, %2;" : "=f"(c) : "f"(a), "f"(b)); return c;
}

// ---------------- K1: prologue (PDL primary) --------------------------------
// 128 blocks x 256 threads; warp per Mu row (8 rows/block), 8 independent
// float4 loads per lane (MLP=8) covering Mu[row, 0:1024]. Few primary blocks
// => all signal launch_dependents almost immediately; MLP=8 => the 4MB read
// is bandwidth- not latency-bound, so thresholds publish early.
__global__ void __launch_bounds__(256) k_pre(const float* __restrict__ Mu,
                                             const float* __restrict__ Sd,
                                             const float* __restrict__ W) {
    asm volatile("griddepcontrol.launch_dependents;" ::: "memory");

    __shared__ float sh[256];
    __shared__ float sh2[256];
    const int t = threadIdx.x;
    const int warp = t >> 5;
    const int lane = t & 31;
    const int row  = blockIdx.x * 8 + warp;

    // 8 independent float4 per lane cover Mu[row, 0:1024]
    const float4* r = (const float4*)(Mu + (size_t)row * D_);
    float4 v[8];
#pragma unroll
    for (int j = 0; j < 8; j++) v[j] = r[lane + 32 * j];

    float sq = 0.0f, sq6 = 0.0f;
#pragma unroll
    for (int j = 0; j < 8; j++) {
        float q = v[j].x * v[j].x + v[j].y * v[j].y
                + v[j].z * v[j].z + v[j].w * v[j].w;
        sq += q;
        if (j < 5) sq6 += q;   // float4 idx < 160 <=> cols < 640
    }
#pragma unroll
    for (int o = 16; o > 0; o >>= 1) {
        sq  += __shfl_xor_sync(0xFFFFFFFFu, sq, o);
        sq6 += __shfl_xor_sync(0xFFFFFFFFu, sq6, o);
    }
    if (lane == 0) {
        atomicMax(&g_max640_bits,  __float_as_int(sq6));
        atomicMax(&g_max1024_bits, __float_as_int(sq));
    }

    if (blockIdx.x == 0) {
        // maxsd2 + exact subnormal z over 1024 (4 per thread)
        float msd = 0.0f;
        const float C = __uint_as_float(CLIP_P_BITS);
        float zp = 0.0f;
#pragma unroll
        for (int i = 0; i < 4; i++) {
            float sd = Sd[t + 256 * i];
            msd = fmaxf(msd, sd * sd);
            // exact: products are multiples of 2^-149, |sum| << 2^-126,
            // so fp32 adds are exact and order-independent.
            zp = add_rn(zp, mul_rn(C, W[t + 256 * i]));
        }
        sh[t] = msd;
        sh2[t] = zp;
        __syncthreads();
        for (int o = 128; o > 0; o >>= 1) {
            if (t < o) {
                sh[t] = fmaxf(sh[t], sh[t + o]);
                sh2[t] = add_rn(sh2[t], sh2[t + o]);
            }
            __syncthreads();
        }
        if (t == 0) {
            g_maxsd2 = sh[0];
            float z = sh2[0];
            float tt = mul_rn(2.0f / 3.0f, z);                // subnormal-safe
            float th = (fabsf(tt) < 1e-5f) ? tt : tanhf(tt);  // tanh(x)==x tiny
            g_yconst = mul_rn(1.7159f, th);
        }
    }
    __syncthreads();

    if (t == 0) {
        __threadfence();
        int c = atomicAdd(&g_count, 1);
        if (c == (int)gridDim.x - 1) {   // last block: publish thresholds
            __threadfence();
            // For any coordinate-prefix S: dist(n,h) >= (||x_S||-||mu_h,S||)^2
            // when ||x_S|| > ||mu_h,S||. Row clips for all h if
            //   ||x_S|| > max_h||mu_h,S|| + sqrt(200*maxsd2*1.001 + 4)
            // (margins cover our fp error AND the reference's GEMM rounding).
            float R = sqrtf(200.0f * g_maxsd2 * 1.001f + 4.0f);
            float a6  = sqrtf(__int_as_float(g_max640_bits))  + R;
            float a10 = sqrtf(__int_as_float(g_max1024_bits)) + R;
            g_th640  = a6 * a6;
            g_th1024 = a10 * a10;
            // reset for next graph replay
            g_max640_bits = 0;
            g_max1024_bits = 0;
            g_count = 0;
            __threadfence();
        }
    }
}

// ---------------- K2: fused main (PDL secondary) ----------------------------
// 2048 blocks x 256 threads; warp per x row. Identical code to R16's k_main;
// ONLY change: min-blocks 5 -> 6 (regs=38 fits 42-reg budget for occ 6, so
// the register allocation is untouched -- pure residency gain).
__global__ void __launch_bounds__(256, 6) k_main(const float* __restrict__ x,
                                                 const float* __restrict__ Mu,
                                                 const float* __restrict__ Sd,
                                                 const float* __restrict__ W,
                                                 float* __restrict__ y,
                                                 float* __restrict__ p) {
    const int warp = threadIdx.x >> 5;
    const int lane = threadIdx.x & 31;
    const int n    = blockIdx.x * 8 + warp;
    const float4* xr = (const float4*)(x + (size_t)n * D_);
    float4* prow = (float4*)(p + (size_t)n * H_);

    // Stage 1: lower bound on ||x_n||^2 from the first 640 elems
    // (sums of squares are monotone, so any prefix is a valid lower bound)
    float4 v[5];
#pragma unroll
    for (int i = 0; i < 5; i++) v[i] = xr[lane + 32 * i];

    // Speculative fill: p[n,:] = exp(-100). Correct for ~every row; a rare
    // unproven row is recomputed and overwritten after verification.
    const float C = __uint_as_float(CLIP_P_BITS);
    const float4 c4 = make_float4(C, C, C, C);
#pragma unroll
    for (int i = 0; i < 8; i++) __stcs(prow + lane + 32 * i, c4);

    float s = 0.0f;
#pragma unroll
    for (int i = 0; i < 5; i++)
        s += v[i].x * v[i].x + v[i].y * v[i].y + v[i].z * v[i].z + v[i].w * v[i].w;
#pragma unroll
    for (int o = 16; o > 0; o >>= 1) s += __shfl_xor_sync(0xFFFFFFFFu, s, o);

    // Wait for k_pre completion (+ memory visibility). HW wait, not a spin.
    asm volatile("griddepcontrol.wait;" ::: "memory");

    bool clipped = (s > g_th640);
    if (!clipped) {
        // Stage 2: extend to prefix 1024 (3 more float4/lane; ~5% of rows)
        float s2 = 0.0f;
#pragma unroll
        for (int i = 5; i < 8; i++) {
            float4 w4 = __ldcs(xr + lane + 32 * i);
            s2 += w4.x * w4.x + w4.y * w4.y + w4.z * w4.z + w4.w * w4.w;
        }
#pragma unroll
        for (int o = 16; o > 0; o >>= 1) s2 += __shfl_xor_sync(0xFFFFFFFFu, s2, o);
        s += s2;
        clipped = (s > g_th1024);
    }

    if (clipped) {
        if (lane == 0) y[n] = g_yconst;   // speculative p row already correct
    } else {
        // Stage 3: exact fallback for an unproven row (insurance; ~never).
        // Computes full x2, and mu2 inline per h (no precomputed tables).
        // Overwrites are same-lane as the speculative fill (lane owns h with
        // ((h>>2)&31)==lane) => same-thread program order, no race.
        float s3 = 0.0f;
#pragma unroll 1
        for (int i = 8; i < 16; i++) {
            float4 w4 = __ldcs(xr + lane + 32 * i);
            s3 += w4.x * w4.x + w4.y * w4.y + w4.z * w4.z + w4.w * w4.w;
        }
#pragma unroll
        for (int o = 16; o > 0; o >>= 1) s3 += __shfl_xor_sync(0xFFFFFFFFu, s3, o);
        s += s3;   // exact ||x_n||^2

        const float* xs = (const float*)xr;
        float z = 0.0f;
#pragma unroll 1
        for (int h = 0; h < H_; h++) {
            const float* mr = Mu + (size_t)h * D_;
            float dot = 0.0f, m2 = 0.0f;
#pragma unroll 1
            for (int k = lane; k < D_; k += 32) {
                float mv = mr[k];
                dot += xs[k] * mv;
                m2  += mv * mv;
            }
#pragma unroll
            for (int o = 16; o > 0; o >>= 1) {
                dot += __shfl_xor_sync(0xFFFFFFFFu, dot, o);
                m2  += __shfl_xor_sync(0xFFFFFFFFu, m2, o);
            }
            float sd = Sd[h];
            float power = -0.5f * (s - 2.0f * dot + m2) / (sd * sd);
            power = fminf(fmaxf(power, -100.0f), 40.0f);
            float pv = expf(power);
            if (lane == ((h >> 2) & 31)) p[(size_t)n * H_ + h] = pv;
            if (lane == 0) z += pv * W[h];
        }
        if (lane == 0) {
            float tt = mul_rn(2.0f / 3.0f, z);
            float th = (fabsf(tt) < 1e-5f) ? tt : tanhf(tt);
            y[n] = mul_rn(1.7159f, th);
        }
    }
}

extern "C" void kernel_launch(void* const* d_in, const int* in_sizes, int n_in,
                              void* d_out, int out_size) {
    const float* x  = (const float*)d_in[0];
    const float* Mu = (const float*)d_in[1];
    const float* Sd = (const float*)d_in[2];
    const float* W  = (const float*)d_in[3];
    float* y = (float*)d_out;          // first N_ elements
    float* p = (float*)d_out + N_;     // then N_*H_ elements

    k_pre<<<128, 256>>>(Mu, Sd, W);

    // k_main with Programmatic Dependent Launch: it begins executing while
    // k_pre is still running; it synchronizes in-kernel via griddepcontrol.wait.
    cudaLaunchAttribute attrs[1];
    attrs[0].id = cudaLaunchAttributeProgrammaticStreamSerialization;
    attrs[0].val.programmaticStreamSerializationAllowed = 1;

    cudaLaunchConfig_t cfg = {};
    cfg.gridDim  = dim3(2048, 1, 1);
    cfg.blockDim = dim3(256, 1, 1);
    cfg.dynamicSmemBytes = 0;
    cfg.stream = 0;            // legacy default stream (the captured stream)
    cfg.attrs = attrs;
    cfg.numAttrs = 1;

    cudaLaunchKernelEx(&cfg, k_main, x, Mu, Sd, W, y, p);
}